// round 10
// baseline (speedup 1.0000x reference)
#include <cuda_runtime.h>
#include <cuda_bf16.h>
#include <cstdint>

// ---------------------------------------------------------------------------
// TransducerPrediction: embed lookup + 2-layer LSTM (Keras gate order i,f,g,o)
// B=64, T=512, EMBED=512, UNITS=1024, 4U=4096.
//
// Pipeline (4 graph nodes):
//   1) gemm_tf32: xz0[BT,4096] = embed[tokens] @ W0 + b0      (gather fused)
//   2) lstm_rec : layer-0 recurrence -> g_h0[BT,1024]
//   3) gemm_tf32: xz1[BT,4096] = g_h0 @ W1 + b1   (reuses g_xz)
//   4) lstm_rec : layer-1 recurrence -> d_out[BT,1024]
// ---------------------------------------------------------------------------

#define BATCH   64
#define SEQT    512
#define EMBED   512
#define UNITS   1024
#define GATES   4096           // 4*UNITS
#define BT      (BATCH*SEQT)   // 32768

#define RT_NCTA    128
#define RT_THREADS 256
// rec kernel smem (floats): UsB 32768 + HsA 8192 + zbuf 64*33
#define REC_SMEM_FLOATS (32768 + 8192 + 64*33)
#define REC_SMEM_BYTES  (REC_SMEM_FLOATS * 4)

// ---- device scratch (static device globals: allowed; runtime alloc is not) ----
__device__ float g_xz[(size_t)BT * GATES];        // 512 MB, reused for both layers
__device__ float g_h0[(size_t)BT * UNITS];        // 128 MB, layer-0 hidden states
__device__ float g_hbuf[2][BATCH * UNITS];        // double-buffered recurrent h
__device__ unsigned g_bar_cnt = 0;
__device__ unsigned g_bar_gen = 0;

// ---------------------------------------------------------------------------
// helpers
// ---------------------------------------------------------------------------
__device__ __forceinline__ float tf32r(float x) {
    unsigned u;
    asm("cvt.rna.tf32.f32 %0, %1;" : "=r"(u) : "f"(x));
    return __uint_as_float(u);
}

__device__ __forceinline__ void mma_m16n8k8_tf32(float* c, float2 a02, float2 a13, float2 b01) {
    unsigned a0 = __float_as_uint(a02.x), a1 = __float_as_uint(a13.x);
    unsigned a2 = __float_as_uint(a02.y), a3 = __float_as_uint(a13.y);
    unsigned b0 = __float_as_uint(b01.x), b1 = __float_as_uint(b01.y);
    asm volatile(
        "mma.sync.aligned.m16n8k8.row.col.f32.tf32.tf32.f32 "
        "{%0,%1,%2,%3}, {%4,%5,%6,%7}, {%8,%9}, {%0,%1,%2,%3};\n"
        : "+f"(c[0]), "+f"(c[1]), "+f"(c[2]), "+f"(c[3])
        : "r"(a0), "r"(a1), "r"(a2), "r"(a3), "r"(b0), "r"(b1));
}

__device__ __forceinline__ float sigmoidf_(float x) {
    return 1.0f / (1.0f + __expf(-x));
}

// Grid barrier over a co-resident grid (<=148 CTAs, 1 CTA/SM).
__device__ __forceinline__ void gridbar(unsigned ncta) {
    __syncthreads();
    if (threadIdx.x == 0) {
        volatile unsigned* genp = (volatile unsigned*)&g_bar_gen;
        unsigned gen = *genp;               // pre-barrier generation (cannot advance
                                            // until this CTA arrives)
        __threadfence();                    // publish this CTA's prior writes
        unsigned old = atomicAdd(&g_bar_cnt, 1u);
        if (old == ncta - 1u) {
            atomicExch(&g_bar_cnt, 0u);
            __threadfence();
            atomicAdd(&g_bar_gen, 1u);      // release
        } else {
            while (*genp == gen) { __nanosleep(64); }
        }
        __threadfence();                    // acquire
    }
    __syncthreads();
}

// ---------------------------------------------------------------------------
// Big GEMM: C[M=BT x 4096] = Arows[M x K] @ Bmat[K x 4096] + bias
// If tokens != nullptr, row r of A is embed[tokens[r], 0:512] (K must be 512).
// Tiles: BM=128, BN=128, BK=32; 8 warps (2m x 4n), warp tile 64x32; tf32 mma.
// Fragment smem packing: float2 slots so each frag load is one LDS.64.
// ---------------------------------------------------------------------------
__global__ __launch_bounds__(256)
void gemm_tf32(const float* __restrict__ A,
               const int*   __restrict__ tokens,
               const float* __restrict__ emb,
               const float* __restrict__ Bmat,
               const float* __restrict__ bias,
               float*       __restrict__ C,
               int K)
{
    __shared__ float2 As[4 * 128 * 4];  // [kc][row][tig] -> (k=tig, k=tig+4)
    __shared__ float2 Bs[4 * 128 * 4];  // [kc][col][tig]

    const int tid  = threadIdx.x;
    const int lane = tid & 31;
    const int wid  = tid >> 5;
    const int gid  = lane >> 2;   // 0..7
    const int tig  = lane & 3;    // 0..3

    const int r0 = blockIdx.y * 128;
    const int n0 = blockIdx.x * 128;
    const int wm = wid >> 2;      // 0..1  (64 rows each)
    const int wn = wid & 3;       // 0..3  (32 cols each)

    float c[4][4][4];
    #pragma unroll
    for (int i = 0; i < 4; i++)
        #pragma unroll
        for (int j = 0; j < 4; j++)
            #pragma unroll
            for (int k = 0; k < 4; k++) c[i][j][k] = 0.0f;

    for (int k0 = 0; k0 < K; k0 += 32) {
        // stage A tile (gather-fused)
        #pragma unroll 4
        for (int idx = tid; idx < 128 * 32; idx += 256) {
            int row = idx >> 5, kk = idx & 31;
            const float* src = tokens
                ? emb + (size_t)tokens[r0 + row] * EMBED
                : A   + (size_t)(r0 + row) * K;
            float v = tf32r(src[k0 + kk]);
            ((float*)&As[((kk >> 3) * 128 + row) * 4 + (kk & 3)])[(kk >> 2) & 1] = v;
        }
        // stage B tile
        #pragma unroll 4
        for (int idx = tid; idx < 32 * 128; idx += 256) {
            int kk = idx >> 7, col = idx & 127;
            float v = tf32r(Bmat[(size_t)(k0 + kk) * GATES + n0 + col]);
            ((float*)&Bs[((kk >> 3) * 128 + col) * 4 + (kk & 3)])[(kk >> 2) & 1] = v;
        }
        __syncthreads();

        #pragma unroll
        for (int kc = 0; kc < 4; kc++) {
            float2 a02[4], a13[4];
            #pragma unroll
            for (int mf = 0; mf < 4; mf++) {
                int m = wm * 64 + mf * 16;
                a02[mf] = As[(kc * 128 + m + gid) * 4 + tig];
                a13[mf] = As[(kc * 128 + m + 8 + gid) * 4 + tig];
            }
            #pragma unroll
            for (int nf = 0; nf < 4; nf++) {
                int n = wn * 32 + nf * 8;
                float2 b01 = Bs[(kc * 128 + n + gid) * 4 + tig];
                #pragma unroll
                for (int mf = 0; mf < 4; mf++)
                    mma_m16n8k8_tf32(c[mf][nf], a02[mf], a13[mf], b01);
            }
        }
        __syncthreads();
    }

    // epilogue: + bias, write fp32
    #pragma unroll
    for (int mf = 0; mf < 4; mf++) {
        int row = r0 + wm * 64 + mf * 16 + gid;
        #pragma unroll
        for (int nf = 0; nf < 4; nf++) {
            int col = n0 + wn * 32 + nf * 8 + tig * 2;
            float bb0 = bias[col], bb1 = bias[col + 1];
            float2 v0 = make_float2(c[mf][nf][0] + bb0, c[mf][nf][1] + bb1);
            float2 v1 = make_float2(c[mf][nf][2] + bb0, c[mf][nf][3] + bb1);
            *(float2*)&C[(size_t)row * GATES + col]       = v0;
            *(float2*)&C[(size_t)(row + 8) * GATES + col] = v1;
        }
    }
}

// ---------------------------------------------------------------------------
// Persistent recurrent kernel. 128 CTAs x 256 threads. CTA owns units
// [u0, u0+8) -> gate columns {g*1024 + u0+j : g in 0..3, j in 0..7} (32 cols).
// U slice [1024 x 32] lives in smem (tf32-rounded fp32) for the whole kernel.
// Cell state c lives in registers (2 (b,u) pairs per thread).
// One grid barrier per timestep; h double-buffered in g_hbuf.
// ---------------------------------------------------------------------------
__global__ __launch_bounds__(RT_THREADS, 1)
void lstm_rec(const float* __restrict__ U,    // [1024][4096] row-major
              const float* __restrict__ xz,   // [B][T][4096]
              float*       __restrict__ hall, // [B][T][1024]
              int T)
{
    extern __shared__ float smem_f[];
    float2* UsB  = (float2*)smem_f;                  // [kcg(128)][col(32)][tig(4)]
    float2* HsA  = (float2*)(smem_f + 32768);        // [kc(16)][b(64)][tig(4)]
    float*  zbuf = smem_f + 32768 + 8192;            // [64][33]

    const int tid  = threadIdx.x;
    const int lane = tid & 31;
    const int wid  = tid >> 5;
    const int gid  = lane >> 2;
    const int tig  = lane & 3;
    const int cta  = blockIdx.x;
    const int u0   = cta * 8;

    // one-time: load + tf32-round the CTA's U slice into smem
    for (int idx = tid; idx < 1024 * 32; idx += RT_THREADS) {
        int k = idx >> 5, cc = idx & 31;
        int G = (cc >> 3) * UNITS + u0 + (cc & 7);
        float v = tf32r(U[(size_t)k * GATES + G]);
        int kcg = k >> 3, kk = k & 7;
        ((float*)&UsB[(kcg * 32 + cc) * 4 + (kk & 3)])[kk >> 2] = v;
    }
    // zero this CTA's slice of hbuf[0]
    for (int p = tid; p < BATCH * 8; p += RT_THREADS) {
        int b = p >> 3, j = p & 7;
        g_hbuf[0][b * UNITS + u0 + j] = 0.0f;
    }
    float creg[2] = {0.0f, 0.0f};   // cell state for pairs p = tid, tid+256

    gridbar(RT_NCTA);

    const int wm = wid >> 1;        // 0..3 : m-tile (16 batches)
    const int wn = wid & 1;         // 0..1 : n-half (16 cols)
    const int m0 = wm * 16;

    for (int t = 0; t < T; ++t) {
        const float* hcur = g_hbuf[t & 1];
        float acc[2][4];
        #pragma unroll
        for (int nt = 0; nt < 2; nt++)
            #pragma unroll
            for (int q = 0; q < 4; q++) acc[nt][q] = 0.0f;

        // z = h @ Uslice : K=1024 in 8 chunks of 128
        for (int chunk = 0; chunk < 8; ++chunk) {
            #pragma unroll 8
            for (int idx = tid; idx < BATCH * 128; idx += RT_THREADS) {
                int b = idx >> 7, kk = idx & 127;
                float v = hcur[b * UNITS + chunk * 128 + kk];
                ((float*)&HsA[((kk >> 3) * 64 + b) * 4 + (kk & 3)])[(kk >> 2) & 1] = v;
            }
            __syncthreads();
            #pragma unroll
            for (int kc = 0; kc < 16; ++kc) {
                float2 a02 = HsA[(kc * 64 + m0 + gid) * 4 + tig];
                float2 a13 = HsA[(kc * 64 + m0 + 8 + gid) * 4 + tig];
                int kcg = chunk * 16 + kc;
                #pragma unroll
                for (int nt = 0; nt < 2; ++nt) {
                    int ncol = wn * 16 + nt * 8 + gid;
                    float2 b01 = UsB[(kcg * 32 + ncol) * 4 + tig];
                    mma_m16n8k8_tf32(acc[nt], a02, a13, b01);
                }
            }
            __syncthreads();
        }

        // spill z to smem for the cross-thread gate combine
        #pragma unroll
        for (int nt = 0; nt < 2; ++nt) {
            int nb = wn * 16 + nt * 8;
            zbuf[(m0 + gid) * 33 + nb + tig * 2]         = acc[nt][0];
            zbuf[(m0 + gid) * 33 + nb + tig * 2 + 1]     = acc[nt][1];
            zbuf[(m0 + 8 + gid) * 33 + nb + tig * 2]     = acc[nt][2];
            zbuf[(m0 + 8 + gid) * 33 + nb + tig * 2 + 1] = acc[nt][3];
        }
        __syncthreads();

        // activations + state update: 512 (b,u) pairs, 2 per thread
        float* hb_next = g_hbuf[(t + 1) & 1];
        #pragma unroll
        for (int j = 0; j < 2; ++j) {
            int p = tid + j * 256;
            int u = p & 7, b = p >> 3;
            size_t base = ((size_t)(b * T + t)) * GATES + u0 + u;
            float zi = zbuf[b * 33 + u]      + xz[base];
            float zf = zbuf[b * 33 + 8 + u]  + xz[base + 1024];
            float zg = zbuf[b * 33 + 16 + u] + xz[base + 2048];
            float zo = zbuf[b * 33 + 24 + u] + xz[base + 3072];
            float ig = sigmoidf_(zi);
            float fg = sigmoidf_(zf);
            float gg = tanhf(zg);
            float og = sigmoidf_(zo);
            float cx = fg * creg[j] + ig * gg;
            creg[j] = cx;
            float h = og * tanhf(cx);
            hall[((size_t)(b * T + t)) * UNITS + u0 + u] = h;       // full fp32 out
            hb_next[b * UNITS + u0 + u] = tf32r(h);                 // tf32 for next GEMM
        }

        gridbar(RT_NCTA);   // all h writes visible before step t+1 reads
    }
}

// ---------------------------------------------------------------------------
// launcher
// ---------------------------------------------------------------------------
extern "C" void kernel_launch(void* const* d_in, const int* in_sizes, int n_in,
                              void* d_out, int out_size)
{
    const int*   tokens = (const int*)  d_in[0];
    const float* emb    = (const float*)d_in[1];
    const float* W0     = (const float*)d_in[2];
    const float* U0     = (const float*)d_in[3];
    const float* b0     = (const float*)d_in[4];
    const float* W1     = (const float*)d_in[5];
    const float* U1     = (const float*)d_in[6];
    const float* b1     = (const float*)d_in[7];
    float* out = (float*)d_out;

    float *xz = nullptr, *h0 = nullptr;
    cudaGetSymbolAddress((void**)&xz, g_xz);
    cudaGetSymbolAddress((void**)&h0, g_h0);

    cudaFuncSetAttribute(lstm_rec, cudaFuncAttributeMaxDynamicSharedMemorySize,
                         REC_SMEM_BYTES);

    dim3 ggrid(GATES / 128, BT / 128);   // (32, 256)

    // Phase A: xz0 = embed[tokens] @ W0 + b0
    gemm_tf32<<<ggrid, 256>>>(nullptr, tokens, emb, W0, b0, xz, EMBED);
    // Phase B: layer-0 recurrence
    lstm_rec<<<RT_NCTA, RT_THREADS, REC_SMEM_BYTES>>>(U0, xz, h0, SEQT);
    // Phase C: xz1 = h0 @ W1 + b1
    gemm_tf32<<<ggrid, 256>>>(h0, nullptr, nullptr, W1, b1, xz, UNITS);
    // Phase D: layer-1 recurrence -> output
    lstm_rec<<<RT_NCTA, RT_THREADS, REC_SMEM_BYTES>>>(U1, xz, out, SEQT);
}

// round 11
// speedup vs baseline: 1.9487x; 1.9487x over previous
#include <cuda_runtime.h>
#include <cuda_bf16.h>
#include <cstdint>

// ---------------------------------------------------------------------------
// TransducerPrediction: embed lookup + 2-layer LSTM (Keras gate order i,f,g,o)
// B=64, T=512, EMBED=512, UNITS=1024, 4U=4096.
//
// Graph (6 nodes):
//   1) gemm_tf32: xz0 = embed[tokens] @ W0 + b0
//   2) zero_cnt
//   3) lstm_rec : layer-0 recurrence -> g_h0
//   4) gemm_tf32: xz1 = g_h0 @ W1 + b1
//   5) zero_cnt
//   6) lstm_rec : layer-1 recurrence -> d_out
//
// lstm_rec redesign vs previous round: cp.async 2-stage chunk pipeline,
// per-chunk-group release/acquire counters instead of a full grid barrier,
// cp.async xz prefetch, 512 threads/CTA.
// ---------------------------------------------------------------------------

#define BATCH   64
#define SEQT    512
#define EMBED   512
#define UNITS   1024
#define GATES   4096
#define BT      (BATCH*SEQT)

#define RT_NCTA    128
#define RT_THREADS 512

// smem layout (bytes):
//   UsB  : 0      .. 131072   (1024x32 tf32 U slice, float2-packed frags)
//   Hs   : 131072 .. 198656   (2 x [64][132] f32 h-chunk buffers)
//   xzs  : 198656 .. 207872   ([64][36] f32 staged gates)
//   zbuf : 207872 .. 216320   ([64][33] f32 z spill)
#define SM_US    0
#define SM_HS    131072
#define SM_HSZ   33792          // 64*132*4 per buffer
#define SM_XZ    198656
#define SM_ZB    207872
#define REC_SMEM_BYTES 216320

// ---- device scratch ----
__device__ __align__(16) float g_xz[(size_t)BT * GATES];
__device__ __align__(16) float g_h0[(size_t)BT * UNITS];
__device__ __align__(16) float g_hbuf[2][BATCH * UNITS];
__device__ unsigned g_cnt[8 * 32];   // 8 chunk-group counters, 128B apart

// ---------------------------------------------------------------------------
// helpers
// ---------------------------------------------------------------------------
__device__ __forceinline__ float tf32r(float x) {
    unsigned u;
    asm("cvt.rna.tf32.f32 %0, %1;" : "=r"(u) : "f"(x));
    return __uint_as_float(u);
}

__device__ __forceinline__ void mma_m16n8k8_tf32(float* c, float2 a02, float2 a13, float2 b01) {
    unsigned a0 = __float_as_uint(a02.x), a1 = __float_as_uint(a13.x);
    unsigned a2 = __float_as_uint(a02.y), a3 = __float_as_uint(a13.y);
    unsigned b0 = __float_as_uint(b01.x), b1 = __float_as_uint(b01.y);
    asm volatile(
        "mma.sync.aligned.m16n8k8.row.col.f32.tf32.tf32.f32 "
        "{%0,%1,%2,%3}, {%4,%5,%6,%7}, {%8,%9}, {%0,%1,%2,%3};\n"
        : "+f"(c[0]), "+f"(c[1]), "+f"(c[2]), "+f"(c[3])
        : "r"(a0), "r"(a1), "r"(a2), "r"(a3), "r"(b0), "r"(b1));
}

__device__ __forceinline__ float sigmoidf_(float x) {
    return 1.0f / (1.0f + __expf(-x));
}

#define CP_ASYNC16(dst_u32, src_ptr) \
    asm volatile("cp.async.cg.shared.global [%0], [%1], 16;\n" \
                 :: "r"(dst_u32), "l"(src_ptr))
#define CP_COMMIT() asm volatile("cp.async.commit_group;\n" ::: "memory")
#define CP_WAIT(n)  asm volatile("cp.async.wait_group %0;\n" :: "n"(n) : "memory")

__device__ __forceinline__ void arrive_release(unsigned* p) {
    asm volatile("red.release.gpu.global.add.u32 [%0], %1;\n" :: "l"(p), "r"(1u) : "memory");
}
__device__ __forceinline__ void poll_acquire(const unsigned* p, unsigned target) {
    unsigned v;
    do {
        asm volatile("ld.acquire.gpu.global.u32 %0, [%1];\n" : "=r"(v) : "l"(p) : "memory");
    } while (v < target);
}

// ---------------------------------------------------------------------------
// Big GEMM: C[M=BT x 4096] = Arows[M x K] @ Bmat[K x 4096] + bias
// (unchanged from the passing round-10 kernel)
// ---------------------------------------------------------------------------
__global__ __launch_bounds__(256)
void gemm_tf32(const float* __restrict__ A,
               const int*   __restrict__ tokens,
               const float* __restrict__ emb,
               const float* __restrict__ Bmat,
               const float* __restrict__ bias,
               float*       __restrict__ C,
               int K)
{
    __shared__ float2 As[4 * 128 * 4];
    __shared__ float2 Bs[4 * 128 * 4];

    const int tid  = threadIdx.x;
    const int lane = tid & 31;
    const int wid  = tid >> 5;
    const int gid  = lane >> 2;
    const int tig  = lane & 3;

    const int r0 = blockIdx.y * 128;
    const int n0 = blockIdx.x * 128;
    const int wm = wid >> 2;
    const int wn = wid & 3;

    float c[4][4][4];
    #pragma unroll
    for (int i = 0; i < 4; i++)
        #pragma unroll
        for (int j = 0; j < 4; j++)
            #pragma unroll
            for (int k = 0; k < 4; k++) c[i][j][k] = 0.0f;

    for (int k0 = 0; k0 < K; k0 += 32) {
        #pragma unroll 4
        for (int idx = tid; idx < 128 * 32; idx += 256) {
            int row = idx >> 5, kk = idx & 31;
            const float* src = tokens
                ? emb + (size_t)tokens[r0 + row] * EMBED
                : A   + (size_t)(r0 + row) * K;
            float v = tf32r(src[k0 + kk]);
            ((float*)&As[((kk >> 3) * 128 + row) * 4 + (kk & 3)])[(kk >> 2) & 1] = v;
        }
        #pragma unroll 4
        for (int idx = tid; idx < 32 * 128; idx += 256) {
            int kk = idx >> 7, col = idx & 127;
            float v = tf32r(Bmat[(size_t)(k0 + kk) * GATES + n0 + col]);
            ((float*)&Bs[((kk >> 3) * 128 + col) * 4 + (kk & 3)])[(kk >> 2) & 1] = v;
        }
        __syncthreads();

        #pragma unroll
        for (int kc = 0; kc < 4; kc++) {
            float2 a02[4], a13[4];
            #pragma unroll
            for (int mf = 0; mf < 4; mf++) {
                int m = wm * 64 + mf * 16;
                a02[mf] = As[(kc * 128 + m + gid) * 4 + tig];
                a13[mf] = As[(kc * 128 + m + 8 + gid) * 4 + tig];
            }
            #pragma unroll
            for (int nf = 0; nf < 4; nf++) {
                int n = wn * 32 + nf * 8;
                float2 b01 = Bs[(kc * 128 + n + gid) * 4 + tig];
                #pragma unroll
                for (int mf = 0; mf < 4; mf++)
                    mma_m16n8k8_tf32(c[mf][nf], a02[mf], a13[mf], b01);
            }
        }
        __syncthreads();
    }

    #pragma unroll
    for (int mf = 0; mf < 4; mf++) {
        int row = r0 + wm * 64 + mf * 16 + gid;
        #pragma unroll
        for (int nf = 0; nf < 4; nf++) {
            int col = n0 + wn * 32 + nf * 8 + tig * 2;
            float bb0 = bias[col], bb1 = bias[col + 1];
            float2 v0 = make_float2(c[mf][nf][0] + bb0, c[mf][nf][1] + bb1);
            float2 v1 = make_float2(c[mf][nf][2] + bb0, c[mf][nf][3] + bb1);
            *(float2*)&C[(size_t)row * GATES + col]       = v0;
            *(float2*)&C[(size_t)(row + 8) * GATES + col] = v1;
        }
    }
}

// ---------------------------------------------------------------------------
// zero the chunk-group counters (runs before each lstm_rec launch)
// ---------------------------------------------------------------------------
__global__ void zero_cnt() {
    if (threadIdx.x < 8 * 32) g_cnt[threadIdx.x] = 0;
}

// ---------------------------------------------------------------------------
// Persistent recurrent kernel. 128 CTAs x 512 threads, 1 CTA/SM.
// CTA owns units [u0,u0+8) -> 32 gate cols; U slice resident in smem.
// Per-chunk-group producer counters replace the full grid barrier.
// ---------------------------------------------------------------------------
__global__ __launch_bounds__(RT_THREADS, 1)
void lstm_rec(const float* __restrict__ U,    // [1024][4096]
              const float* __restrict__ xz,   // [B][T][4096]
              float*       __restrict__ hall, // [B][T][1024]
              int T)
{
    extern __shared__ char smem_c[];
    float2* UsB  = (float2*)(smem_c + SM_US);
    float*  Hs   = (float*) (smem_c + SM_HS);
    float*  xzs  = (float*) (smem_c + SM_XZ);
    float*  zbuf = (float*) (smem_c + SM_ZB);
    const unsigned smem_u32 = (unsigned)__cvta_generic_to_shared(smem_c);

    const int tid  = threadIdx.x;
    const int lane = tid & 31;
    const int wid  = tid >> 5;
    const int gid  = lane >> 2;
    const int tig  = lane & 3;
    const int cta  = blockIdx.x;
    const int u0   = cta * 8;
    const int grp  = cta >> 4;          // this CTA's chunk group (h units u0/128)

    // one-time: load + tf32-round the CTA's U slice into smem (frag-packed)
    for (int idx = tid; idx < 1024 * 32; idx += RT_THREADS) {
        int k = idx >> 5, cc = idx & 31;
        int G = (cc >> 3) * UNITS + u0 + (cc & 7);
        float v = tf32r(U[(size_t)k * GATES + G]);
        int kcg = k >> 3, kk = k & 7;
        ((float*)&UsB[(kcg * 32 + cc) * 4 + (kk & 3)])[kk >> 2] = v;
    }

    // produce h_0 = 0 for this CTA's slice, then arrive
    {
        int b = tid >> 3, u = tid & 7;       // 512 threads = 64 b x 8 u
        g_hbuf[0][b * UNITS + u0 + u] = 0.0f;
    }
    __syncthreads();
    if (tid == 0) arrive_release(&g_cnt[grp * 32]);

    float creg = 0.0f;                       // cell state, 1 (b,u) pair/thread
    const int ab = tid >> 3, au = tid & 7;   // activation pair

    const int wm = wid >> 2;                 // 0..3 : 16 batches
    const int wn = wid & 3;                  // 0..3 : 8 cols
    const int m0 = wm * 16;

    for (int t = 0; t < T; ++t) {
        const float* hcur = g_hbuf[t & 1];
        const unsigned target = 16u * (unsigned)(t + 1);

        // -- stage xz gates for this step (no h dependency; overlaps chunk loop)
        {
            int b = tid >> 3, r = tid & 7, g = r >> 1, h4 = r & 1;
            const float* src = xz + ((size_t)(b * T + t)) * GATES + g * UNITS + u0 + h4 * 4;
            unsigned dst = smem_u32 + SM_XZ + (b * 36 + g * 8 + h4 * 4) * 4;
            CP_ASYNC16(dst, src);
            CP_COMMIT();                      // group: XZ
        }

        // -- prefetch h chunks 0,1
        #pragma unroll
        for (int pc = 0; pc < 2; ++pc) {
            poll_acquire(&g_cnt[pc * 32], target);
            #pragma unroll
            for (int j = 0; j < 4; ++j) {
                int i = tid + j * RT_THREADS;         // 2048 16B copies
                int row = i >> 5, seg = i & 31;
                unsigned dst = smem_u32 + SM_HS + (pc & 1) * SM_HSZ + row * 528 + seg * 16;
                CP_ASYNC16(dst, hcur + row * UNITS + pc * 128 + seg * 4);
            }
            CP_COMMIT();                      // groups: H0, H1
        }

        float acc[4] = {0.0f, 0.0f, 0.0f, 0.0f};

        for (int c = 0; c < 8; ++c) {
            if (c < 7) { CP_WAIT(1); } else { CP_WAIT(0); }
            __syncthreads();                  // chunk c visible CTA-wide

            const float* H = Hs + (c & 1) * (SM_HSZ / 4);
            #pragma unroll
            for (int kc = 0; kc < 16; ++kc) {
                const float* r0p = H + (m0 + gid) * 132 + kc * 8;
                const float* r1p = H + (m0 + 8 + gid) * 132 + kc * 8;
                float2 a02 = make_float2(r0p[tig], r0p[tig + 4]);
                float2 a13 = make_float2(r1p[tig], r1p[tig + 4]);
                float2 b01 = UsB[(((c * 16 + kc) * 32) + wn * 8 + gid) * 4 + tig];
                mma_m16n8k8_tf32(acc, a02, a13, b01);
            }

            if (c + 2 < 8) {
                __syncthreads();              // buffer (c&1) free for reuse
                poll_acquire(&g_cnt[(c + 2) * 32], target);
                #pragma unroll
                for (int j = 0; j < 4; ++j) {
                    int i = tid + j * RT_THREADS;
                    int row = i >> 5, seg = i & 31;
                    unsigned dst = smem_u32 + SM_HS + (c & 1) * SM_HSZ + row * 528 + seg * 16;
                    CP_ASYNC16(dst, hcur + row * UNITS + (c + 2) * 128 + seg * 4);
                }
                CP_COMMIT();
            }
        }

        // -- spill z to smem for cross-thread gate combine
        {
            int col = wn * 8 + tig * 2;
            zbuf[(m0 + gid) * 33 + col]         = acc[0];
            zbuf[(m0 + gid) * 33 + col + 1]     = acc[1];
            zbuf[(m0 + 8 + gid) * 33 + col]     = acc[2];
            zbuf[(m0 + 8 + gid) * 33 + col + 1] = acc[3];
        }
        __syncthreads();

        // -- activations + state update (xz already staged in smem)
        {
            float zi = zbuf[ab * 33 + au]      + xzs[ab * 36 + au];
            float zf = zbuf[ab * 33 + 8 + au]  + xzs[ab * 36 + 8 + au];
            float zg = zbuf[ab * 33 + 16 + au] + xzs[ab * 36 + 16 + au];
            float zo = zbuf[ab * 33 + 24 + au] + xzs[ab * 36 + 24 + au];
            float ig = sigmoidf_(zi);
            float fg = sigmoidf_(zf);
            float gg = tanhf(zg);
            float og = sigmoidf_(zo);
            float cx = fg * creg + ig * gg;
            creg = cx;
            float h = og * tanhf(cx);
            hall[((size_t)(ab * T + t)) * UNITS + u0 + au] = h;
            g_hbuf[(t + 1) & 1][ab * UNITS + u0 + au] = tf32r(h);
        }
        __syncthreads();                      // all slice writes done; xzs free
        if (tid == 0) arrive_release(&g_cnt[grp * 32]);
    }
}

// ---------------------------------------------------------------------------
// launcher
// ---------------------------------------------------------------------------
extern "C" void kernel_launch(void* const* d_in, const int* in_sizes, int n_in,
                              void* d_out, int out_size)
{
    const int*   tokens = (const int*)  d_in[0];
    const float* emb    = (const float*)d_in[1];
    const float* W0     = (const float*)d_in[2];
    const float* U0     = (const float*)d_in[3];
    const float* b0     = (const float*)d_in[4];
    const float* W1     = (const float*)d_in[5];
    const float* U1     = (const float*)d_in[6];
    const float* b1     = (const float*)d_in[7];
    float* out = (float*)d_out;

    float *xz = nullptr, *h0 = nullptr;
    cudaGetSymbolAddress((void**)&xz, g_xz);
    cudaGetSymbolAddress((void**)&h0, g_h0);

    cudaFuncSetAttribute(lstm_rec, cudaFuncAttributeMaxDynamicSharedMemorySize,
                         REC_SMEM_BYTES);

    dim3 ggrid(GATES / 128, BT / 128);

    // Phase A: xz0 = embed[tokens] @ W0 + b0
    gemm_tf32<<<ggrid, 256>>>(nullptr, tokens, emb, W0, b0, xz, EMBED);
    // Phase B: layer-0 recurrence
    zero_cnt<<<1, 256>>>();
    lstm_rec<<<RT_NCTA, RT_THREADS, REC_SMEM_BYTES>>>(U0, xz, h0, SEQT);
    // Phase C: xz1 = h0 @ W1 + b1
    gemm_tf32<<<ggrid, 256>>>(h0, nullptr, nullptr, W1, b1, xz, UNITS);
    // Phase D: layer-1 recurrence -> output
    zero_cnt<<<1, 256>>>();
    lstm_rec<<<RT_NCTA, RT_THREADS, REC_SMEM_BYTES>>>(U1, xz, out, SEQT);
}